// round 3
// baseline (speedup 1.0000x reference)
#include <cuda_runtime.h>
#include <cstdint>

// ---------------------------------------------------------------------------
// GeometricPositionalFingerprinter — Round 3: persistent CTA + cp.async.bulk
// double-buffered SMEM pipeline.
//
// Input : pentachora [V, 5, 128] f32   (V = in_sizes[0]/640)
// Output: cantor fingerprint [V] f32
//
// One CTA per SM (persistent). Each CTA loops over tiles of 32 pentachora
// (81920 B). A 2-stage SMEM ring is filled by cp.async.bulk (issued by thread
// 0, completion via mbarrier expect_tx), so DRAM request depth is independent
// of warp count / register pressure.
//
// Compute: 8 lanes per pentachoron (256 thr -> 32 pentachora per stage).
// Lane l of group g reads float4 columns {l, l+8, l+16, l+24} of each vertex
// row from SMEM -> each 8-lane quarter-warp phase reads 128 contiguous bytes
// (conflict-free LDS.128). 3-level XOR butterfly reduces the 20 statistics;
// lane 0 of each group stages them in SMEM; warp 0 then runs the scalar
// epilogue once per pentachoron (no redundant MUFU work).
// ---------------------------------------------------------------------------

static constexpr int PENT_PER_TILE = 32;
static constexpr int TILE_FLOATS   = PENT_PER_TILE * 640;     // 20480
static constexpr int TILE_BYTES    = TILE_FLOATS * 4;         // 81920
static constexpr int NUM_STAGES    = 2;
static constexpr int STATS_STRIDE  = 21;                      // pad: gcd(21,32)=1
static constexpr int STATS_OFF     = NUM_STAGES * TILE_BYTES; // 163840
static constexpr int STATS_FLOATS  = PENT_PER_TILE * STATS_STRIDE; // 672 per buf
static constexpr int MBAR_OFF      = STATS_OFF + NUM_STAGES * STATS_FLOATS * 4;
static constexpr int SMEM_TOTAL    = MBAR_OFF + NUM_STAGES * 8;

__device__ __forceinline__ uint32_t smem_u32(const void* p) {
    return (uint32_t)__cvta_generic_to_shared(p);
}

__device__ __forceinline__ void mbar_init(uint32_t mbar, uint32_t count) {
    asm volatile("mbarrier.init.shared.b64 [%0], %1;" :: "r"(mbar), "r"(count)
                 : "memory");
}

__device__ __forceinline__ void mbar_expect_tx(uint32_t mbar, uint32_t bytes) {
    asm volatile("mbarrier.arrive.expect_tx.shared.b64 _, [%0], %1;"
                 :: "r"(mbar), "r"(bytes) : "memory");
}

__device__ __forceinline__ void mbar_wait(uint32_t mbar, uint32_t parity) {
    asm volatile(
        "{\n\t"
        ".reg .pred P;\n\t"
        "WAIT_%=:\n\t"
        "mbarrier.try_wait.parity.acquire.cta.shared::cta.b64 P, [%0], %1, 0x989680;\n\t"
        "@!P bra WAIT_%=;\n\t"
        "}" :: "r"(mbar), "r"(parity) : "memory");
}

__device__ __forceinline__ void bulk_g2s(uint32_t dst_smem, const void* src,
                                         uint32_t bytes, uint32_t mbar) {
    asm volatile(
        "cp.async.bulk.shared::cluster.global.mbarrier::complete_tx::bytes "
        "[%0], [%1], %2, [%3];"
        :: "r"(dst_smem), "l"(src), "r"(bytes), "r"(mbar) : "memory");
}

__device__ __forceinline__ float sigmoid_pos(float x) {
    // x >= 0 always. ~2 ulp regardless of fast-math flags.
    if (x > 18.0f) return 1.0f;
    float t = -x;
    float kf = rintf(t * 1.4426950408889634f);
    float r = fmaf(-kf, 0.693145751953125f, t);
    r = fmaf(-kf, 1.428606765330187e-06f, r);
    float p = fmaf(r, 1.38888889e-3f, 8.33333333e-3f);
    p = fmaf(r, p, 4.16666667e-2f);
    p = fmaf(r, p, 1.66666667e-1f);
    p = fmaf(r, p, 0.5f);
    p = fmaf(r, p, 1.0f);
    p = fmaf(r, p, 1.0f);
    int ki = (int)kf;
    float scale = __int_as_float((ki + 127) << 23);
    float e = p * scale;
    return __fdiv_rn(1.0f, __fadd_rn(1.0f, e));
}

// Scalar epilogue — numerics byte-identical to R1 (which measured 7.86e-4).
__device__ __forceinline__ float epilogue(const float acc[15], const float cd[5]) {
    float gm[5][5];
    {
        int k = 0;
#pragma unroll
        for (int i = 0; i < 5; ++i)
#pragma unroll
            for (int j = i; j < 5; ++j) {
                gm[i][j] = acc[k];
                gm[j][i] = acc[k];
                ++k;
            }
    }
    // Edge statistics (triu order = np.triu_indices(5, k=1))
    float e[10];
    {
        int m = 0;
#pragma unroll
        for (int i = 0; i < 5; ++i)
#pragma unroll
            for (int j = i + 1; j < 5; ++j) {
                float ds = __fsub_rn(__fadd_rn(gm[i][i], gm[j][j]),
                                     __fmul_rn(2.0f, gm[i][j]));
                ds = fmaxf(ds, 0.0f);
                e[m++] = __fsqrt_rn(ds);
            }
    }
    float esum = 0.0f;
#pragma unroll
    for (int i = 0; i < 10; ++i) esum = __fadd_rn(esum, e[i]);
    float mean_edge = __fdiv_rn(esum, 10.0f);
    float ess = 0.0f;
#pragma unroll
    for (int i = 0; i < 10; ++i) {
        float d = __fsub_rn(e[i], mean_edge);
        ess = fmaf(d, d, ess);
    }
    float std_edge = __fsqrt_rn(__fdiv_rn(ess, 9.0f));
    float ratio = __fdiv_rn(std_edge, __fadd_rn(mean_edge, 1e-6f));

    // Vertex spread (ddof=1)
    float dc[5];
    float csum = 0.0f;
#pragma unroll
    for (int v = 0; v < 5; ++v) {
        dc[v] = __fsqrt_rn(cd[v]);
        csum = __fadd_rn(csum, dc[v]);
    }
    float cmean = __fdiv_rn(csum, 5.0f);
    float css = 0.0f;
#pragma unroll
    for (int v = 0; v < 5; ++v) {
        float d = __fsub_rn(dc[v], cmean);
        css = fmaf(d, d, css);
    }
    float spread = __fsqrt_rn(__fdiv_rn(css, 4.0f));

    // Volume via 4x4 edge-vector Gram det (sigmoid saturates to 1.0f)
    float G[4][4];
#pragma unroll
    for (int i = 0; i < 4; ++i)
#pragma unroll
        for (int j = 0; j < 4; ++j)
            G[i][j] = (gm[i + 1][j + 1] - gm[0][i + 1]) - (gm[0][j + 1] - gm[0][0]);

    float d2233 = G[2][2] * G[3][3] - G[2][3] * G[3][2];
    float d2133 = G[2][1] * G[3][3] - G[2][3] * G[3][1];
    float d2132 = G[2][1] * G[3][2] - G[2][2] * G[3][1];
    float d2033 = G[2][0] * G[3][3] - G[2][3] * G[3][0];
    float d2032 = G[2][0] * G[3][2] - G[2][2] * G[3][0];
    float d2031 = G[2][0] * G[3][1] - G[2][1] * G[3][0];
    float c0 = G[1][1] * d2233 - G[1][2] * d2133 + G[1][3] * d2132;
    float c1 = G[1][0] * d2233 - G[1][2] * d2033 + G[1][3] * d2032;
    float c2 = G[1][0] * d2133 - G[1][1] * d2033 + G[1][3] * d2031;
    float c3 = G[1][0] * d2132 - G[1][1] * d2032 + G[1][2] * d2031;
    float det = G[0][0] * c0 - G[0][1] * c1 + G[0][2] * c2 - G[0][3] * c3;
    float vol = __fsqrt_rn(fmaxf(__fdiv_rn(det, 576.0f), 0.0f));

    float s1 = sigmoid_pos(__fmul_rn(vol, 10.0f));
    float s2 = sigmoid_pos(ratio);
    float s3 = sigmoid_pos(spread);
    float seed = __fadd_rn(__fadd_rn(__fmul_rn(s1, 0.4f), __fmul_rn(s2, 0.3f)),
                           __fmul_rn(s3, 0.3f));

    float x = fminf(fmaxf(seed, 1e-6f), 0.999999f);

    float cantor = 0.0f;
    float factor = 0.5f;
#pragma unroll
    for (int it = 0; it < 8; ++it) {
        float xs = __fmul_rn(x, 3.0f);
        int d = (int)xs;
        x = __fsub_rn(xs, (float)d);
        if (d == 2) cantor = __fadd_rn(cantor, factor);
        factor *= 0.5f;
    }
    return fminf(fmaxf(cantor, 0.0f), 1.0f);
}

__global__ void __launch_bounds__(256, 1)
gpf_tma_kernel(const float* __restrict__ pent, float* __restrict__ out,
               int V, int n_tiles)
{
    extern __shared__ char smem[];
    const int tid = threadIdx.x;
    const int bid = blockIdx.x;
    const int G   = gridDim.x;

    const uint32_t sbase     = smem_u32(smem);
    const uint32_t mbar_base = sbase + MBAR_OFF;
    float* stats_base = reinterpret_cast<float*>(smem + STATS_OFF);

    // Number of tiles this CTA owns (tiles bid, bid+G, bid+2G, ...)
    int my_n = (bid < n_tiles) ? (n_tiles - bid + G - 1) / G : 0;

    if (tid == 0) {
        mbar_init(mbar_base + 0, 1);
        mbar_init(mbar_base + 8, 1);
        asm volatile("fence.proxy.async.shared::cta;" ::: "memory");
    }
    __syncthreads();

    // Prologue: fill both pipeline stages.
    if (tid == 0) {
        int pre = my_n < NUM_STAGES ? my_n : NUM_STAGES;
        for (int s = 0; s < pre; ++s) {
            int t = bid + s * G;
            int m = V - t * PENT_PER_TILE;
            if (m > PENT_PER_TILE) m = PENT_PER_TILE;
            uint32_t bytes = (uint32_t)m * 2560u;
            mbar_expect_tx(mbar_base + s * 8, bytes);
            bulk_g2s(sbase + s * TILE_BYTES,
                     pent + (size_t)t * TILE_FLOATS, bytes, mbar_base + s * 8);
        }
    }

    const int g2 = tid >> 3;   // pentachoron within tile (0..31)
    const int l  = tid & 7;    // lane within 8-lane group

    for (int k = 0; k < my_n; ++k) {
        const int buf = k & 1;
        const uint32_t parity = (uint32_t)((k >> 1) & 1);
        mbar_wait(mbar_base + buf * 8, parity);

        // ---- compute from SMEM stage buffer ----
        const float4* bptr =
            reinterpret_cast<const float4*>(smem + (size_t)buf * TILE_BYTES)
            + g2 * 160 + l;

        float acc[15];
        float cd[5];
#pragma unroll
        for (int i = 0; i < 15; ++i) acc[i] = 0.0f;
#pragma unroll
        for (int v = 0; v < 5; ++v) cd[v] = 0.0f;

#pragma unroll
        for (int c = 0; c < 4; ++c) {
            float4 a[5];
#pragma unroll
            for (int v = 0; v < 5; ++v) a[v] = bptr[v * 32 + c * 8];

            float cx = (((a[0].x + a[1].x) + (a[2].x + a[3].x)) + a[4].x) * 0.2f;
            float cy = (((a[0].y + a[1].y) + (a[2].y + a[3].y)) + a[4].y) * 0.2f;
            float cz = (((a[0].z + a[1].z) + (a[2].z + a[3].z)) + a[4].z) * 0.2f;
            float cw = (((a[0].w + a[1].w) + (a[2].w + a[3].w)) + a[4].w) * 0.2f;

            int kk = 0;
#pragma unroll
            for (int i = 0; i < 5; ++i) {
#pragma unroll
                for (int j = i; j < 5; ++j) {
                    float t = acc[kk];
                    t = fmaf(a[i].x, a[j].x, t);
                    t = fmaf(a[i].y, a[j].y, t);
                    t = fmaf(a[i].z, a[j].z, t);
                    t = fmaf(a[i].w, a[j].w, t);
                    acc[kk] = t;
                    ++kk;
                }
            }
#pragma unroll
            for (int v = 0; v < 5; ++v) {
                float dx = a[v].x - cx;
                float dy = a[v].y - cy;
                float dz = a[v].z - cz;
                float dw = a[v].w - cw;
                float t = cd[v];
                t = fmaf(dx, dx, t);
                t = fmaf(dy, dy, t);
                t = fmaf(dz, dz, t);
                t = fmaf(dw, dw, t);
                cd[v] = t;
            }
        }

        // 3-level butterfly within the 8-lane group
#pragma unroll
        for (int i = 0; i < 15; ++i) {
            acc[i] += __shfl_xor_sync(0xffffffffu, acc[i], 1);
            acc[i] += __shfl_xor_sync(0xffffffffu, acc[i], 2);
            acc[i] += __shfl_xor_sync(0xffffffffu, acc[i], 4);
        }
#pragma unroll
        for (int v = 0; v < 5; ++v) {
            cd[v] += __shfl_xor_sync(0xffffffffu, cd[v], 1);
            cd[v] += __shfl_xor_sync(0xffffffffu, cd[v], 2);
            cd[v] += __shfl_xor_sync(0xffffffffu, cd[v], 4);
        }

        // Stage the 20 statistics (double-buffered; overwritten at k+2 only,
        // and every thread passes the k+1 __syncthreads in between, so warp0's
        // epilogue read below is race-free without a second barrier).
        if (l == 0) {
            float* st = stats_base + buf * STATS_FLOATS + g2 * STATS_STRIDE;
#pragma unroll
            for (int i = 0; i < 15; ++i) st[i] = acc[i];
#pragma unroll
            for (int v = 0; v < 5; ++v) st[15 + v] = cd[v];
        }

        __syncthreads();  // stage reads done + stats visible

        // Refill this buffer for tile k+2.
        if (tid == 0 && k + NUM_STAGES < my_n) {
            int t2 = bid + (k + NUM_STAGES) * G;
            int m = V - t2 * PENT_PER_TILE;
            if (m > PENT_PER_TILE) m = PENT_PER_TILE;
            uint32_t bytes = (uint32_t)m * 2560u;
            mbar_expect_tx(mbar_base + buf * 8, bytes);
            bulk_g2s(sbase + buf * TILE_BYTES,
                     pent + (size_t)t2 * TILE_FLOATS, bytes,
                     mbar_base + buf * 8);
        }

        // Warp 0: scalar epilogue, one pentachoron per thread.
        if (tid < PENT_PER_TILE) {
            int t = bid + k * G;
            int pidx = t * PENT_PER_TILE + tid;
            if (pidx < V) {
                const float* st = stats_base + buf * STATS_FLOATS
                                + tid * STATS_STRIDE;
                float a2[15], c2[5];
#pragma unroll
                for (int i = 0; i < 15; ++i) a2[i] = st[i];
#pragma unroll
                for (int v = 0; v < 5; ++v) c2[v] = st[15 + v];
                out[pidx] = epilogue(a2, c2);
            }
        }
    }
}

extern "C" void kernel_launch(void* const* d_in, const int* in_sizes, int n_in,
                              void* d_out, int out_size)
{
    const float* p = (const float*)d_in[0];
    float* out = (float*)d_out;
    int V = in_sizes[0] / 640;                 // [V, 5, 128]
    int n_tiles = (V + PENT_PER_TILE - 1) / PENT_PER_TILE;

    int dev = 0, sms = 148;
    cudaGetDevice(&dev);
    cudaDeviceGetAttribute(&sms, cudaDevAttrMultiProcessorCount, dev);

    int grid = sms < n_tiles ? sms : n_tiles;
    if (grid < 1) grid = 1;

    cudaFuncSetAttribute(gpf_tma_kernel,
                         cudaFuncAttributeMaxDynamicSharedMemorySize,
                         SMEM_TOTAL);
    gpf_tma_kernel<<<grid, 256, SMEM_TOTAL>>>(p, out, V, n_tiles);
}

// round 4
// speedup vs baseline: 1.1621x; 1.1621x over previous
#include <cuda_runtime.h>
#include <cstdint>

// ---------------------------------------------------------------------------
// GeometricPositionalFingerprinter — Round 4: LDG streaming (R1 skeleton) with
// a reduced 15-accumulator formulation to fit 50 regs -> 5 CTAs/SM.
//
// Input : pentachora [V, 5, 128] f32  (V = in_sizes[0]/640)
// Output: cantor fingerprint [V] f32
//
// 4 lanes per pentachoron (8 pentachora/warp), float4 columns, 8 chunks.
// Accumulate per lane:
//   - 10 pairwise squared distances  dist2[i<j] = sum (a_i - a_j)^2
//     (direct diff form: no gram cancellation -> better conditioned)
//   - 5 squared distances to the centroid
// 2-level XOR butterfly reduce; all 4 lanes run the scalar epilogue (free
// under SIMT), lane 0 stores. Volume Gram rebuilt from distances:
//   G[i][j] = 0.5*(d(0,i+1) + d(0,j+1) - d(i+1,j+1)),  vol^2 = det(G)/576.
// ---------------------------------------------------------------------------

__device__ __forceinline__ float sigmoid_pos(float x) {
    // x >= 0 always. ~2 ulp regardless of fast-math flags.
    if (x > 18.0f) return 1.0f;
    float t = -x;
    float kf = rintf(t * 1.4426950408889634f);
    float r = fmaf(-kf, 0.693145751953125f, t);
    r = fmaf(-kf, 1.428606765330187e-06f, r);
    float p = fmaf(r, 1.38888889e-3f, 8.33333333e-3f);
    p = fmaf(r, p, 4.16666667e-2f);
    p = fmaf(r, p, 1.66666667e-1f);
    p = fmaf(r, p, 0.5f);
    p = fmaf(r, p, 1.0f);
    p = fmaf(r, p, 1.0f);
    int ki = (int)kf;
    float scale = __int_as_float((ki + 127) << 23);
    float e = p * scale;
    return __fdiv_rn(1.0f, __fadd_rn(1.0f, e));
}

__global__ void __launch_bounds__(256, 5)
gpf_kernel(const float* __restrict__ pent, float* __restrict__ out, int V)
{
    int tid = blockIdx.x * 256 + threadIdx.x;
    int g = tid >> 2;        // pentachoron index
    int s = tid & 3;         // sublane within 4-lane group
    if (g >= V) return;

    const float4* __restrict__ base =
        reinterpret_cast<const float4*>(pent) + (size_t)g * 160 + s;

    float ed[10];   // pairwise squared distances, triu(5,k=1) order
    float cd[5];    // squared distance to centroid per vertex
#pragma unroll
    for (int i = 0; i < 10; ++i) ed[i] = 0.0f;
#pragma unroll
    for (int v = 0; v < 5; ++v) cd[v] = 0.0f;

#pragma unroll
    for (int c = 0; c < 8; ++c) {
        float4 a[5];
#pragma unroll
        for (int v = 0; v < 5; ++v) a[v] = base[v * 32 + c * 4];

        // centroid chunk
        float cx = (((a[0].x + a[1].x) + (a[2].x + a[3].x)) + a[4].x) * 0.2f;
        float cy = (((a[0].y + a[1].y) + (a[2].y + a[3].y)) + a[4].y) * 0.2f;
        float cz = (((a[0].z + a[1].z) + (a[2].z + a[3].z)) + a[4].z) * 0.2f;
        float cw = (((a[0].w + a[1].w) + (a[2].w + a[3].w)) + a[4].w) * 0.2f;

        // 10 pairwise squared distances (direct difference form)
        int m = 0;
#pragma unroll
        for (int i = 0; i < 5; ++i) {
#pragma unroll
            for (int j = i + 1; j < 5; ++j) {
                float dx = a[i].x - a[j].x;
                float dy = a[i].y - a[j].y;
                float dz = a[i].z - a[j].z;
                float dw = a[i].w - a[j].w;
                float t = ed[m];
                t = fmaf(dx, dx, t);
                t = fmaf(dy, dy, t);
                t = fmaf(dz, dz, t);
                t = fmaf(dw, dw, t);
                ed[m] = t;
                ++m;
            }
        }
        // centroid distances
#pragma unroll
        for (int v = 0; v < 5; ++v) {
            float dx = a[v].x - cx;
            float dy = a[v].y - cy;
            float dz = a[v].z - cz;
            float dw = a[v].w - cw;
            float t = cd[v];
            t = fmaf(dx, dx, t);
            t = fmaf(dy, dy, t);
            t = fmaf(dz, dz, t);
            t = fmaf(dw, dw, t);
            cd[v] = t;
        }
    }

    // Butterfly reduce across the 4-lane group
#pragma unroll
    for (int i = 0; i < 10; ++i) {
        ed[i] += __shfl_xor_sync(0xffffffffu, ed[i], 1);
        ed[i] += __shfl_xor_sync(0xffffffffu, ed[i], 2);
    }
#pragma unroll
    for (int v = 0; v < 5; ++v) {
        cd[v] += __shfl_xor_sync(0xffffffffu, cd[v], 1);
        cd[v] += __shfl_xor_sync(0xffffffffu, cd[v], 2);
    }

    // --- Edge statistics (ed[] already in np.triu_indices(5, k=1) order) ---
    float e[10];
#pragma unroll
    for (int i = 0; i < 10; ++i) e[i] = __fsqrt_rn(fmaxf(ed[i], 0.0f));
    float esum = 0.0f;
#pragma unroll
    for (int i = 0; i < 10; ++i) esum = __fadd_rn(esum, e[i]);
    float mean_edge = __fdiv_rn(esum, 10.0f);
    float ess = 0.0f;
#pragma unroll
    for (int i = 0; i < 10; ++i) {
        float d = __fsub_rn(e[i], mean_edge);
        ess = fmaf(d, d, ess);
    }
    float std_edge = __fsqrt_rn(__fdiv_rn(ess, 9.0f));   // ddof=1
    float ratio = __fdiv_rn(std_edge, __fadd_rn(mean_edge, 1e-6f));

    // --- Vertex spread (ddof=1 std of distances to centroid) ---
    float dc[5];
    float csum = 0.0f;
#pragma unroll
    for (int v = 0; v < 5; ++v) {
        dc[v] = __fsqrt_rn(cd[v]);
        csum = __fadd_rn(csum, dc[v]);
    }
    float cmean = __fdiv_rn(csum, 5.0f);
    float css = 0.0f;
#pragma unroll
    for (int v = 0; v < 5; ++v) {
        float d = __fsub_rn(dc[v], cmean);
        css = fmaf(d, d, css);
    }
    float spread = __fsqrt_rn(__fdiv_rn(css, 4.0f));

    // --- Volume from distances via 4x4 edge-vector Gram det ---
    // d0[i] = dist2(v0, v_{i+1}); dij = dist2(v_{i+1}, v_{j+1})
    // G[i][j] = 0.5*(d0[i] + d0[j] - dij);  vol^2 = det(G)/576
    // sigmoid(10*vol) saturates to exactly 1.0f for this data (vol ~ O(1000)),
    // so fp32 rounding in det is invisible in the output.
    float d0[4] = { ed[0], ed[1], ed[2], ed[3] };
    // pair distances among v1..v4: (1,2)=ed[4] (1,3)=ed[5] (1,4)=ed[6]
    //                              (2,3)=ed[7] (2,4)=ed[8] (3,4)=ed[9]
    float G[4][4];
#pragma unroll
    for (int i = 0; i < 4; ++i) G[i][i] = d0[i];
    G[0][1] = G[1][0] = 0.5f * ((d0[0] + d0[1]) - ed[4]);
    G[0][2] = G[2][0] = 0.5f * ((d0[0] + d0[2]) - ed[5]);
    G[0][3] = G[3][0] = 0.5f * ((d0[0] + d0[3]) - ed[6]);
    G[1][2] = G[2][1] = 0.5f * ((d0[1] + d0[2]) - ed[7]);
    G[1][3] = G[3][1] = 0.5f * ((d0[1] + d0[3]) - ed[8]);
    G[2][3] = G[3][2] = 0.5f * ((d0[2] + d0[3]) - ed[9]);

    float d2233 = G[2][2] * G[3][3] - G[2][3] * G[3][2];
    float d2133 = G[2][1] * G[3][3] - G[2][3] * G[3][1];
    float d2132 = G[2][1] * G[3][2] - G[2][2] * G[3][1];
    float d2033 = G[2][0] * G[3][3] - G[2][3] * G[3][0];
    float d2032 = G[2][0] * G[3][2] - G[2][2] * G[3][0];
    float d2031 = G[2][0] * G[3][1] - G[2][1] * G[3][0];
    float c0 = G[1][1] * d2233 - G[1][2] * d2133 + G[1][3] * d2132;
    float c1 = G[1][0] * d2233 - G[1][2] * d2033 + G[1][3] * d2032;
    float c2 = G[1][0] * d2133 - G[1][1] * d2033 + G[1][3] * d2031;
    float c3 = G[1][0] * d2132 - G[1][1] * d2032 + G[1][2] * d2031;
    float det = G[0][0] * c0 - G[0][1] * c1 + G[0][2] * c2 - G[0][3] * c3;
    float vol = __fsqrt_rn(fmaxf(__fdiv_rn(det, 576.0f), 0.0f));

    // --- Seed (reference op order) ---
    float s1 = sigmoid_pos(__fmul_rn(vol, 10.0f));
    float s2 = sigmoid_pos(ratio);
    float s3 = sigmoid_pos(spread);
    float seed = __fadd_rn(__fadd_rn(__fmul_rn(s1, 0.4f), __fmul_rn(s2, 0.3f)),
                           __fmul_rn(s3, 0.3f));

    float x = fminf(fmaxf(seed, 1e-6f), 0.999999f);

    // --- Ternary Cantor digits ---
    float cantor = 0.0f;
    float factor = 0.5f;
#pragma unroll
    for (int it = 0; it < 8; ++it) {
        float xs = __fmul_rn(x, 3.0f);
        int d = (int)xs;
        x = __fsub_rn(xs, (float)d);
        if (d == 2) cantor = __fadd_rn(cantor, factor);
        factor *= 0.5f;
    }

    if (s == 0) out[g] = fminf(fmaxf(cantor, 0.0f), 1.0f);
}

extern "C" void kernel_launch(void* const* d_in, const int* in_sizes, int n_in,
                              void* d_out, int out_size)
{
    const float* p = (const float*)d_in[0];
    float* out = (float*)d_out;
    int V = in_sizes[0] / 640;                 // [V, 5, 128]
    long long total = (long long)V * 4;        // 4 lanes per pentachoron
    int threads = 256;
    int blocks = (int)((total + threads - 1) / threads);
    gpf_kernel<<<blocks, threads>>>(p, out, V);
}

// round 5
// speedup vs baseline: 1.1785x; 1.0141x over previous
#include <cuda_runtime.h>
#include <cstdint>

// ---------------------------------------------------------------------------
// GeometricPositionalFingerprinter — Round 5: 10-accumulator formulation.
//
// Input : pentachora [V, 5, 128] f32  (V = in_sizes[0]/640)
// Output: cantor fingerprint [V] f32
//
// 4 lanes per pentachoron (8 pentachora/warp), float4 columns, 8 chunks.
// Hot loop accumulates ONLY the 10 pairwise squared distances (direct diff
// form). Everything else is derived in the epilogue:
//   - edges: e = sqrt(ed)
//   - volume: Gram from distances, det/576
//   - spread: centroid identity  |p_v - c|^2 = (5*S_v - T)/25,
//     S_v = row sum of distance matrix, T = sum of all 10 distances.
// Live set ~36 regs -> 6 CTAs/SM (launch_bounds(256,6)), no spills.
// ed accumulation order is bit-identical to R4.
// ---------------------------------------------------------------------------

__device__ __forceinline__ float sigmoid_pos(float x) {
    // x >= 0 always. ~2 ulp regardless of fast-math flags.
    if (x > 18.0f) return 1.0f;
    float t = -x;
    float kf = rintf(t * 1.4426950408889634f);
    float r = fmaf(-kf, 0.693145751953125f, t);
    r = fmaf(-kf, 1.428606765330187e-06f, r);
    float p = fmaf(r, 1.38888889e-3f, 8.33333333e-3f);
    p = fmaf(r, p, 4.16666667e-2f);
    p = fmaf(r, p, 1.66666667e-1f);
    p = fmaf(r, p, 0.5f);
    p = fmaf(r, p, 1.0f);
    p = fmaf(r, p, 1.0f);
    int ki = (int)kf;
    float scale = __int_as_float((ki + 127) << 23);
    float e = p * scale;
    return __fdiv_rn(1.0f, __fadd_rn(1.0f, e));
}

__global__ void __launch_bounds__(256, 6)
gpf_kernel(const float* __restrict__ pent, float* __restrict__ out, int V)
{
    int tid = blockIdx.x * 256 + threadIdx.x;
    int g = tid >> 2;        // pentachoron index
    int s = tid & 3;         // sublane within 4-lane group
    if (g >= V) return;

    const float4* __restrict__ base =
        reinterpret_cast<const float4*>(pent) + (size_t)g * 160 + s;

    float ed[10];   // pairwise squared distances, triu(5,k=1) order
#pragma unroll
    for (int i = 0; i < 10; ++i) ed[i] = 0.0f;

#pragma unroll
    for (int c = 0; c < 8; ++c) {
        float4 a[5];
#pragma unroll
        for (int v = 0; v < 5; ++v) a[v] = base[v * 32 + c * 4];

        int m = 0;
#pragma unroll
        for (int i = 0; i < 5; ++i) {
#pragma unroll
            for (int j = i + 1; j < 5; ++j) {
                float dx = a[i].x - a[j].x;
                float dy = a[i].y - a[j].y;
                float dz = a[i].z - a[j].z;
                float dw = a[i].w - a[j].w;
                float t = ed[m];
                t = fmaf(dx, dx, t);
                t = fmaf(dy, dy, t);
                t = fmaf(dz, dz, t);
                t = fmaf(dw, dw, t);
                ed[m] = t;
                ++m;
            }
        }
    }

    // Butterfly reduce across the 4-lane group
#pragma unroll
    for (int i = 0; i < 10; ++i) {
        ed[i] += __shfl_xor_sync(0xffffffffu, ed[i], 1);
        ed[i] += __shfl_xor_sync(0xffffffffu, ed[i], 2);
    }

    // --- Edge statistics (ed[] already in np.triu_indices(5, k=1) order) ---
    float e[10];
#pragma unroll
    for (int i = 0; i < 10; ++i) e[i] = __fsqrt_rn(fmaxf(ed[i], 0.0f));
    float esum = 0.0f;
#pragma unroll
    for (int i = 0; i < 10; ++i) esum = __fadd_rn(esum, e[i]);
    float mean_edge = __fdiv_rn(esum, 10.0f);
    float ess = 0.0f;
#pragma unroll
    for (int i = 0; i < 10; ++i) {
        float d = __fsub_rn(e[i], mean_edge);
        ess = fmaf(d, d, ess);
    }
    float std_edge = __fsqrt_rn(__fdiv_rn(ess, 9.0f));   // ddof=1
    float ratio = __fdiv_rn(std_edge, __fadd_rn(mean_edge, 1e-6f));

    // --- Vertex spread via centroid identity ---
    // S_v = sum_j dist2(v,j);  T = sum of all 10;  cd[v] = (5*S_v - T)/25
    // pairs: (0,1)=0 (0,2)=1 (0,3)=2 (0,4)=3 (1,2)=4 (1,3)=5 (1,4)=6
    //        (2,3)=7 (2,4)=8 (3,4)=9
    float T = __fadd_rn(__fadd_rn(__fadd_rn(__fadd_rn(ed[0], ed[1]),
                                            __fadd_rn(ed[2], ed[3])),
                                  __fadd_rn(__fadd_rn(ed[4], ed[5]),
                                            __fadd_rn(ed[6], ed[7]))),
                        __fadd_rn(ed[8], ed[9]));
    float S0 = __fadd_rn(__fadd_rn(ed[0], ed[1]), __fadd_rn(ed[2], ed[3]));
    float S1 = __fadd_rn(__fadd_rn(ed[0], ed[4]), __fadd_rn(ed[5], ed[6]));
    float S2 = __fadd_rn(__fadd_rn(ed[1], ed[4]), __fadd_rn(ed[7], ed[8]));
    float S3 = __fadd_rn(__fadd_rn(ed[2], ed[5]), __fadd_rn(ed[7], ed[9]));
    float S4 = __fadd_rn(__fadd_rn(ed[3], ed[6]), __fadd_rn(ed[8], ed[9]));

    float dc[5];
    float Sv[5] = { S0, S1, S2, S3, S4 };
    float csum = 0.0f;
#pragma unroll
    for (int v = 0; v < 5; ++v) {
        float cdv = __fmul_rn(__fsub_rn(__fmul_rn(5.0f, Sv[v]), T), 0.04f);
        dc[v] = __fsqrt_rn(fmaxf(cdv, 0.0f));
        csum = __fadd_rn(csum, dc[v]);
    }
    float cmean = __fdiv_rn(csum, 5.0f);
    float css = 0.0f;
#pragma unroll
    for (int v = 0; v < 5; ++v) {
        float d = __fsub_rn(dc[v], cmean);
        css = fmaf(d, d, css);
    }
    float spread = __fsqrt_rn(__fdiv_rn(css, 4.0f));

    // --- Volume from distances via 4x4 edge-vector Gram det ---
    // G[i][j] = 0.5*(d0[i] + d0[j] - dij);  vol^2 = det(G)/576
    // sigmoid(10*vol) saturates to exactly 1.0f for this data.
    float d0[4] = { ed[0], ed[1], ed[2], ed[3] };
    float G[4][4];
#pragma unroll
    for (int i = 0; i < 4; ++i) G[i][i] = d0[i];
    G[0][1] = G[1][0] = 0.5f * ((d0[0] + d0[1]) - ed[4]);
    G[0][2] = G[2][0] = 0.5f * ((d0[0] + d0[2]) - ed[5]);
    G[0][3] = G[3][0] = 0.5f * ((d0[0] + d0[3]) - ed[6]);
    G[1][2] = G[2][1] = 0.5f * ((d0[1] + d0[2]) - ed[7]);
    G[1][3] = G[3][1] = 0.5f * ((d0[1] + d0[3]) - ed[8]);
    G[2][3] = G[3][2] = 0.5f * ((d0[2] + d0[3]) - ed[9]);

    float d2233 = G[2][2] * G[3][3] - G[2][3] * G[3][2];
    float d2133 = G[2][1] * G[3][3] - G[2][3] * G[3][1];
    float d2132 = G[2][1] * G[3][2] - G[2][2] * G[3][1];
    float d2033 = G[2][0] * G[3][3] - G[2][3] * G[3][0];
    float d2032 = G[2][0] * G[3][2] - G[2][2] * G[3][0];
    float d2031 = G[2][0] * G[3][1] - G[2][1] * G[3][0];
    float c0 = G[1][1] * d2233 - G[1][2] * d2133 + G[1][3] * d2132;
    float c1 = G[1][0] * d2233 - G[1][2] * d2033 + G[1][3] * d2032;
    float c2 = G[1][0] * d2133 - G[1][1] * d2033 + G[1][3] * d2031;
    float c3 = G[1][0] * d2132 - G[1][1] * d2032 + G[1][2] * d2031;
    float det = G[0][0] * c0 - G[0][1] * c1 + G[0][2] * c2 - G[0][3] * c3;
    float vol = __fsqrt_rn(fmaxf(__fdiv_rn(det, 576.0f), 0.0f));

    // --- Seed (reference op order) ---
    float s1 = sigmoid_pos(__fmul_rn(vol, 10.0f));
    float s2 = sigmoid_pos(ratio);
    float s3 = sigmoid_pos(spread);
    float seed = __fadd_rn(__fadd_rn(__fmul_rn(s1, 0.4f), __fmul_rn(s2, 0.3f)),
                           __fmul_rn(s3, 0.3f));

    float x = fminf(fmaxf(seed, 1e-6f), 0.999999f);

    // --- Ternary Cantor digits ---
    float cantor = 0.0f;
    float factor = 0.5f;
#pragma unroll
    for (int it = 0; it < 8; ++it) {
        float xs = __fmul_rn(x, 3.0f);
        int d = (int)xs;
        x = __fsub_rn(xs, (float)d);
        if (d == 2) cantor = __fadd_rn(cantor, factor);
        factor *= 0.5f;
    }

    if (s == 0) out[g] = fminf(fmaxf(cantor, 0.0f), 1.0f);
}

extern "C" void kernel_launch(void* const* d_in, const int* in_sizes, int n_in,
                              void* d_out, int out_size)
{
    const float* p = (const float*)d_in[0];
    float* out = (float*)d_out;
    int V = in_sizes[0] / 640;                 // [V, 5, 128]
    long long total = (long long)V * 4;        // 4 lanes per pentachoron
    int threads = 256;
    int blocks = (int)((total + threads - 1) / threads);
    gpf_kernel<<<blocks, threads>>>(p, out, V);
}